// round 5
// baseline (speedup 1.0000x reference)
#include <cuda_runtime.h>

// NormSelfAttention: B=4,H=16,N=2048,D=128
//   Qf = elu(Q)+1 ; Kf = (elu(K)+1)*mask ; Vf = V*mask
//   KV[d,e] = sum_n Kf[n,d]*Vf[n,e] ; out[n,e] = sum_d Qf[n,d]*KV[d,e]
//   out = out * rsqrt(mean_e(out^2) + 1e-6)

#define HH     16
#define BH     64
#define SEQ    2048
#define DD     128
#define SPLITS 8
#define NSPLIT (SEQ / SPLITS)   // 256
#define CHUNK  16

// Scratch (device globals: allocation rules forbid cudaMalloc)
__device__ float g_kvpart[(size_t)BH * SPLITS * DD * DD];  // 32 MB
__device__ float g_kv[(size_t)BH * DD * DD];               //  4 MB

typedef unsigned long long u64_t;

static __device__ __forceinline__ u64_t pk2(float a, float b) {
    u64_t r;
    asm("mov.b64 %0, {%1, %2};"
        : "=l"(r) : "r"(__float_as_uint(a)), "r"(__float_as_uint(b)));
    return r;
}
static __device__ __forceinline__ u64_t ffma2(u64_t a, u64_t b, u64_t c) {
    u64_t d;
    asm("fma.rn.f32x2 %0, %1, %2, %3;" : "=l"(d) : "l"(a), "l"(b), "l"(c));
    return d;
}
static __device__ __forceinline__ void upk2(u64_t v, float& lo, float& hi) {
    unsigned int l, h;
    asm("mov.b64 {%0, %1}, %2;" : "=r"(l), "=r"(h) : "l"(v));
    lo = __uint_as_float(l);
    hi = __uint_as_float(h);
}
static __device__ __forceinline__ float actf(float x) {
    // elu(x)+1 : x>0 -> x+1 ; else exp(x)
    return x > 0.0f ? x + 1.0f : __expf(x);
}

// ---------------------------------------------------------------------------
// Phase 1: KV partials. grid (SPLITS, BH), 256 threads.
// Block computes full 128x128 KV over its 256-row n-slice.
// Thread microtile: 8 e (j, broadcast side) x 8 d (as 4 f32x2 pairs).
// ---------------------------------------------------------------------------
__global__ __launch_bounds__(256, 2)
void kv_kernel(const float* __restrict__ K, const float* __restrict__ V,
               const float* __restrict__ mask) {
    const int split = blockIdx.x;
    const int bh    = blockIdx.y;
    const int b     = bh >> 4;           // H = 16
    const int nbase = split * NSPLIT;

    __shared__ float4 Ks[CHUNK][32];     // [n][d/4]
    __shared__ float4 Vs[CHUNK][32];     // [n][e/4]

    const int tid = threadIdx.x;
    const int tx  = tid & 15;            // e group
    const int ty  = tid >> 4;            // d group
    const int e0  = tx * 8;
    const int d0  = ty * 8;

    u64_t acc[8][4];
#pragma unroll
    for (int j = 0; j < 8; j++)
#pragma unroll
        for (int p = 0; p < 4; p++) acc[j][p] = 0ull;

    const float4* K4 = ((const float4*)K) + (size_t)bh * (SEQ * DD / 4);
    const float4* V4 = ((const float4*)V) + (size_t)bh * (SEQ * DD / 4);
    const float*  mrow = mask + b * SEQ;

    for (int c = 0; c < NSPLIT; c += CHUNK) {
        __syncthreads();
#pragma unroll
        for (int it = 0; it < 2; it++) {
            int flat = tid + it * 256;       // 512 float4 per operand
            int row  = flat >> 5;
            int col  = flat & 31;
            int n    = nbase + c + row;
            float m  = mrow[n];
            float4 kv = K4[(size_t)n * 32 + col];
            kv.x = actf(kv.x) * m; kv.y = actf(kv.y) * m;
            kv.z = actf(kv.z) * m; kv.w = actf(kv.w) * m;
            Ks[row][col] = kv;
            float4 vv = V4[(size_t)n * 32 + col];
            vv.x *= m; vv.y *= m; vv.z *= m; vv.w *= m;
            Vs[row][col] = vv;
        }
        __syncthreads();
#pragma unroll
        for (int n = 0; n < CHUNK; n++) {
            float4 ka = Ks[n][ty * 2];
            float4 kb = Ks[n][ty * 2 + 1];
            float4 va = Vs[n][tx * 2];
            float4 vb = Vs[n][tx * 2 + 1];
            u64_t kp[4] = { pk2(ka.x, ka.y), pk2(ka.z, ka.w),
                            pk2(kb.x, kb.y), pk2(kb.z, kb.w) };
            float vf[8] = { va.x, va.y, va.z, va.w, vb.x, vb.y, vb.z, vb.w };
#pragma unroll
            for (int j = 0; j < 8; j++) {
                u64_t vj = pk2(vf[j], vf[j]);
#pragma unroll
                for (int p = 0; p < 4; p++)
                    acc[j][p] = ffma2(vj, kp[p], acc[j][p]);
            }
        }
    }

    // acc[j][p] = ( KV[d0+2p][e0+j] , KV[d0+2p+1][e0+j] )
    float* out = g_kvpart + ((size_t)bh * SPLITS + split) * (DD * DD);
#pragma unroll
    for (int p = 0; p < 4; p++) {
        float lo[8], hi[8];
#pragma unroll
        for (int j = 0; j < 8; j++) upk2(acc[j][p], lo[j], hi[j]);
        float* r0 = out + (size_t)(d0 + 2 * p)     * DD + e0;
        float* r1 = out + (size_t)(d0 + 2 * p + 1) * DD + e0;
        *(float4*)(r0)     = make_float4(lo[0], lo[1], lo[2], lo[3]);
        *(float4*)(r0 + 4) = make_float4(lo[4], lo[5], lo[6], lo[7]);
        *(float4*)(r1)     = make_float4(hi[0], hi[1], hi[2], hi[3]);
        *(float4*)(r1 + 4) = make_float4(hi[4], hi[5], hi[6], hi[7]);
    }
}

// ---------------------------------------------------------------------------
// Phase 1.5: reduce 8 split partials -> g_kv. 262144 float4 total.
// ---------------------------------------------------------------------------
__global__ __launch_bounds__(256)
void reduce_kernel() {
    int idx = blockIdx.x * 256 + threadIdx.x;      // over float4 of g_kv
    const float4* in  = (const float4*)g_kvpart;
    float4*       out = (float4*)g_kv;
    int bh  = idx >> 12;                           // 4096 float4 per bh
    int off = idx & 4095;
    float4 s = make_float4(0.f, 0.f, 0.f, 0.f);
#pragma unroll
    for (int sp = 0; sp < SPLITS; sp++) {
        float4 v = in[((size_t)bh * SPLITS + sp) * 4096 + off];
        s.x += v.x; s.y += v.y; s.z += v.z; s.w += v.w;
    }
    out[idx] = s;
}

// ---------------------------------------------------------------------------
// Phase 2: out = Qf @ KV + fused RMS norm. grid (16, BH), 256 threads.
// Smem: Qs[128][130] (pad 130 -> 8-row stride hits distinct banks),
//       KVs[128][128] (float4), red[128][16], scale[128]. ~137.5 KB dynamic.
// Thread microtile: 8 n (i, broadcast side) x 8 e (4 f32x2 pairs).
// ---------------------------------------------------------------------------
#define QPAD 130
#define SMEM2_FLOATS (128 * QPAD + 128 * 128 + 128 * 16 + 128)
#define SMEM2_BYTES  (SMEM2_FLOATS * 4)

__global__ __launch_bounds__(256)
void out_kernel(const float* __restrict__ Q, float* __restrict__ O) {
    const int ntile = blockIdx.x;
    const int bh    = blockIdx.y;
    const int n0t   = ntile * 128;
    const int tid   = threadIdx.x;
    const int tx    = tid & 15;          // e group
    const int ty    = tid >> 4;          // n group
    const int e0    = tx * 8;
    const int nl0   = ty * 8;

    extern __shared__ float sm[];
    float*  Qs    = sm;                               // 128*130
    float4* KVs   = (float4*)(sm + 128 * QPAD);       // 128*32 float4
    float*  red   = sm + 128 * QPAD + 128 * 128;      // 128*16
    float*  scale = red + 128 * 16;                   // 128

    // Load KV tile (already reduced)
    const float4* kvg = ((const float4*)g_kv) + (size_t)bh * (DD * DD / 4);
#pragma unroll
    for (int it = 0; it < 16; it++)
        KVs[tid + it * 256] = kvg[tid + it * 256];

    // Load + activate Q tile into padded smem (coalesced gmem read)
    const float4* Q4 = ((const float4*)Q) + ((size_t)bh * SEQ + n0t) * (DD / 4);
#pragma unroll
    for (int it = 0; it < 16; it++) {
        int flat = tid + it * 256;       // 4096 float4
        int row  = flat >> 5;
        int col  = flat & 31;
        float4 q = Q4[flat];
        float* dst = Qs + row * QPAD + col * 4;
        dst[0] = actf(q.x); dst[1] = actf(q.y);
        dst[2] = actf(q.z); dst[3] = actf(q.w);
    }
    __syncthreads();

    u64_t acc[8][4];
#pragma unroll
    for (int i = 0; i < 8; i++)
#pragma unroll
        for (int p = 0; p < 4; p++) acc[i][p] = 0ull;

#pragma unroll 4
    for (int d = 0; d < DD; d++) {
        float4 ca = KVs[d * 32 + tx * 2];
        float4 cb = KVs[d * 32 + tx * 2 + 1];
        u64_t cp[4] = { pk2(ca.x, ca.y), pk2(ca.z, ca.w),
                        pk2(cb.x, cb.y), pk2(cb.z, cb.w) };
#pragma unroll
        for (int i = 0; i < 8; i++) {
            float qv = Qs[(nl0 + i) * QPAD + d];
            u64_t qp = pk2(qv, qv);
#pragma unroll
            for (int p = 0; p < 4; p++)
                acc[i][p] = ffma2(qp, cp[p], acc[i][p]);
        }
    }

    // Partial sum-of-squares per row -> smem reduce across 16 tx threads
#pragma unroll
    for (int i = 0; i < 8; i++) {
        float ss = 0.f;
#pragma unroll
        for (int p = 0; p < 4; p++) {
            float lo, hi; upk2(acc[i][p], lo, hi);
            ss += lo * lo + hi * hi;
        }
        red[(nl0 + i) * 16 + tx] = ss;
    }
    __syncthreads();
    if (tid < 128) {
        float s = 0.f;
#pragma unroll
        for (int j = 0; j < 16; j++) s += red[tid * 16 + j];
        scale[tid] = rsqrtf(s * (1.0f / 128.0f) + 1e-6f);
    }
    __syncthreads();

    float* Obase = O + ((size_t)bh * SEQ + n0t) * DD;
#pragma unroll
    for (int i = 0; i < 8; i++) {
        float sc = scale[nl0 + i];
        float* orow = Obase + (size_t)(nl0 + i) * DD + e0;
#pragma unroll
        for (int p = 0; p < 4; p++) {
            float lo, hi; upk2(acc[i][p], lo, hi);
            *(float2*)(orow + 2 * p) = make_float2(lo * sc, hi * sc);
        }
    }
}

// ---------------------------------------------------------------------------
extern "C" void kernel_launch(void* const* d_in, const int* in_sizes, int n_in,
                              void* d_out, int out_size) {
    const float* Q    = (const float*)d_in[0];
    const float* K    = (const float*)d_in[1];
    const float* V    = (const float*)d_in[2];
    const float* mask = (const float*)d_in[3];
    float*       O    = (float*)d_out;

    // Opt-in to >48KB dynamic smem for phase 2 (idempotent; host-side, legal
    // during graph capture since it is not a stream operation).
    cudaFuncSetAttribute(out_kernel, cudaFuncAttributeMaxDynamicSharedMemorySize,
                         SMEM2_BYTES);

    kv_kernel<<<dim3(SPLITS, BH), 256>>>(K, V, mask);
    reduce_kernel<<<(BH * DD * DD / 4) / 256, 256>>>();
    out_kernel<<<dim3(SEQ / 128, BH), 256, SMEM2_BYTES>>>(Q, O);
}

// round 7
// speedup vs baseline: 1.3048x; 1.3048x over previous
#include <cuda_runtime.h>
#include <cuda_bf16.h>

// NormSelfAttention B=4,H=16,N=2048,D=128 via mma.sync bf16x3 (HMMA path;
// tcgen05 is unavailable at the harness's compute_103 virtual arch).
//  Phase1: KVpart[d,e] = sum_n (elu(K)+1)*m [n,d] * (V*m)[n,e]   split-K=4
//  Mid:    KV = sum splits -> pre-swizzled bf16 hi/lo tiles
//  Phase2: out[n,e] = sum_d (elu(Q)+1)[n,d]*KV[d,e]; fused RMS norm

#define SEQ    2048
#define NBH    64
#define SPLITS 4

__device__ float    g_kvpart[(size_t)NBH * SPLITS * 128 * 128];  // 16 MB
__device__ unsigned g_kvh[(size_t)NBH * 8192];                   // 2 MB
__device__ unsigned g_kvl[(size_t)NBH * 8192];                   // 2 MB

typedef unsigned u32;
typedef unsigned long long u64;

static __device__ __forceinline__ u32 smem_u32(const void* p) {
    u32 a;
    asm("{ .reg .u64 t; cvta.to.shared.u64 t, %1; cvt.u32.u64 %0, t; }"
        : "=r"(a) : "l"(p));
    return a;
}
static __device__ __forceinline__ float actf(float x) {
    return x > 0.0f ? x + 1.0f : __expf(x);
}
// hi = {bf16(x1),bf16(x0)}, lo = packed bf16 residuals (residual exact in f32)
static __device__ __forceinline__ void hilo(float x0, float x1, u32& h, u32& l) {
    asm("cvt.rn.bf16x2.f32 %0, %1, %2;" : "=r"(h) : "f"(x1), "f"(x0));
    float f0 = __uint_as_float(h << 16);
    float f1 = __uint_as_float(h & 0xFFFF0000u);
    asm("cvt.rn.bf16x2.f32 %0, %1, %2;" : "=r"(l) : "f"(x1 - f1), "f"(x0 - f0));
}
// 256B-row tile, xor-swizzled 16B units. col in b16 elements.
static __device__ __forceinline__ int sw_addr(int row, int col) {
    return (row << 8) + ((((col >> 3) ^ (row & 7)) << 4)) + ((col & 7) << 1);
}
// 512B-row f32 staging tile. col in f32 elements.
static __device__ __forceinline__ int os_addr(int row, int col) {
    return (row << 9) + ((((col >> 2) ^ (row & 7)) << 4)) + ((col & 3) << 2);
}

#define LDSM4(r0, r1, r2, r3, a)                                              \
    asm volatile("ldmatrix.sync.aligned.m8n8.x4.shared.b16 {%0,%1,%2,%3}, [%4];" \
        : "=r"(r0), "=r"(r1), "=r"(r2), "=r"(r3) : "r"(a))
#define LDSM4T(r0, r1, r2, r3, a)                                             \
    asm volatile("ldmatrix.sync.aligned.m8n8.x4.trans.shared.b16 {%0,%1,%2,%3}, [%4];" \
        : "=r"(r0), "=r"(r1), "=r"(r2), "=r"(r3) : "r"(a))

static __device__ __forceinline__ void mma16816(float* c, const u32* a, const u32* b) {
    asm volatile(
        "mma.sync.aligned.m16n8k16.row.col.f32.bf16.bf16.f32 "
        "{%0,%1,%2,%3}, {%4,%5,%6,%7}, {%8,%9}, {%0,%1,%2,%3};"
        : "+f"(c[0]), "+f"(c[1]), "+f"(c[2]), "+f"(c[3])
        : "r"(a[0]), "r"(a[1]), "r"(a[2]), "r"(a[3]), "r"(b[0]), "r"(b[1]));
}

// ---------------------------------------------------------------------------
// Phase 1. grid (4, 64), 256 thr (8 warps: 2 d x 4 e; warp tile 64d x 32e).
// smem: KH 0, KL 8K, VH 16K, VL 24K — tiles [32 n][128 bf16] swizzled.
// ---------------------------------------------------------------------------
__global__ __launch_bounds__(256, 1)
void phase1(const float* __restrict__ K, const float* __restrict__ V,
            const float* __restrict__ mask) {
    __shared__ char sm1[32768];
    const u32 sb = smem_u32(sm1);
    const int tid = threadIdx.x, lane = tid & 31, wid = tid >> 5;
    const int split = blockIdx.x, bh = blockIdx.y, b = bh >> 4;
    const int d_base = (wid >> 2) * 64, e_base = (wid & 3) * 32;

    float acc[4][4][4];
#pragma unroll
    for (int i = 0; i < 4; i++)
#pragma unroll
        for (int j = 0; j < 4; j++)
#pragma unroll
            for (int q = 0; q < 4; q++) acc[i][j][q] = 0.f;

    const float4* K4 = (const float4*)K + (size_t)bh * (SEQ * 32) + (size_t)split * (512 * 32);
    const float4* V4 = (const float4*)V + (size_t)bh * (SEQ * 32) + (size_t)split * (512 * 32);
    const float*  mrow = mask + b * SEQ + split * 512;

    // ldmatrix lane address components
    const int a_row_l = ((lane >> 4) & 1) * 8 + (lane & 7);   // trans A (groups: a1=col+8)
    const int a_col_l = ((lane >> 3) & 1) * 8;
    const int b_row_l = ((lane >> 3) & 1) * 8 + (lane & 7);   // trans B (groups: b1=row+8)
    const int b_col_l = ((lane >> 4) & 1) * 8;

    for (int c = 0; c < 16; c++) {
        if (c) __syncthreads();
#pragma unroll
        for (int it = 0; it < 4; it++) {
            int flat = tid + it * 256;
            int row  = flat >> 5;        // n local 0..31
            int fd   = flat & 31;        // d/4
            int n    = c * 32 + row;
            float m  = mrow[n];
            float4 kq = K4[(size_t)n * 32 + fd];
            float4 vq = V4[(size_t)n * 32 + fd];
            u32 h0, l0, h1, l1;
            int off = sw_addr(row, fd * 4);
            hilo(actf(kq.x) * m, actf(kq.y) * m, h0, l0);
            hilo(actf(kq.z) * m, actf(kq.w) * m, h1, l1);
            *(u64*)(sm1 + off)         = (u64)h0 | ((u64)h1 << 32);
            *(u64*)(sm1 + 8192 + off)  = (u64)l0 | ((u64)l1 << 32);
            hilo(vq.x * m, vq.y * m, h0, l0);
            hilo(vq.z * m, vq.w * m, h1, l1);
            *(u64*)(sm1 + 16384 + off) = (u64)h0 | ((u64)h1 << 32);
            *(u64*)(sm1 + 24576 + off) = (u64)l0 | ((u64)l1 << 32);
        }
        __syncthreads();
#pragma unroll
        for (int ks = 0; ks < 2; ks++) {
            int n0 = ks * 16;
            u32 ah[4][4], al[4][4];
#pragma unroll
            for (int mt = 0; mt < 4; mt++) {
                u32 ad = sb + sw_addr(n0 + a_row_l, d_base + mt * 16 + a_col_l);
                LDSM4T(ah[mt][0], ah[mt][1], ah[mt][2], ah[mt][3], ad);
                LDSM4T(al[mt][0], al[mt][1], al[mt][2], al[mt][3], ad + 8192);
            }
            u32 bhf[4][2], blf[4][2];
#pragma unroll
            for (int h = 0; h < 2; h++) {
                u32 ad = sb + 16384 + sw_addr(n0 + b_row_l, e_base + h * 16 + b_col_l);
                u32 r0, r1, r2, r3;
                LDSM4T(r0, r1, r2, r3, ad);
                bhf[2 * h][0] = r0; bhf[2 * h][1] = r1;
                bhf[2 * h + 1][0] = r2; bhf[2 * h + 1][1] = r3;
                LDSM4T(r0, r1, r2, r3, ad + 8192);
                blf[2 * h][0] = r0; blf[2 * h][1] = r1;
                blf[2 * h + 1][0] = r2; blf[2 * h + 1][1] = r3;
            }
#pragma unroll
            for (int mt = 0; mt < 4; mt++)
#pragma unroll
                for (int nt = 0; nt < 4; nt++) {
                    mma16816(acc[mt][nt], ah[mt], bhf[nt]);
                    mma16816(acc[mt][nt], ah[mt], blf[nt]);
                    mma16816(acc[mt][nt], al[mt], bhf[nt]);
                }
        }
    }

    float* outp = g_kvpart + ((size_t)(bh * SPLITS + split)) * 16384;
#pragma unroll
    for (int mt = 0; mt < 4; mt++)
#pragma unroll
        for (int nt = 0; nt < 4; nt++) {
            int d1 = d_base + mt * 16 + (lane >> 2);
            int e  = e_base + nt * 8 + (lane & 3) * 2;
            *(float2*)(outp + d1 * 128 + e) =
                make_float2(acc[mt][nt][0], acc[mt][nt][1]);
            *(float2*)(outp + (d1 + 8) * 128 + e) =
                make_float2(acc[mt][nt][2], acc[mt][nt][3]);
        }
}

// ---------------------------------------------------------------------------
// Mid. grid 64, 256 thr. Sum 4 splits, emit pre-swizzled bf16 hi/lo tiles.
// ---------------------------------------------------------------------------
__global__ __launch_bounds__(256)
void midk() {
    const int bh = blockIdx.x, tid = threadIdx.x;
    const float* src = g_kvpart + (size_t)bh * (SPLITS * 16384);
    u32* oh = g_kvh + (size_t)bh * 8192;
    u32* ol = g_kvl + (size_t)bh * 8192;
#pragma unroll 4
    for (int i = 0; i < 32; i++) {
        int p = tid + i * 256;           // 0..8191
        int d = p >> 6, e = (p & 63) * 2;
        float sx = 0.f, sy = 0.f;
#pragma unroll
        for (int s = 0; s < SPLITS; s++) {
            float2 v = *(const float2*)(src + s * 16384 + d * 128 + e);
            sx += v.x; sy += v.y;
        }
        u32 h, l; hilo(sx, sy, h, l);
        int idx = sw_addr(d, e) >> 2;
        oh[idx] = h; ol[idx] = l;
    }
}

// ---------------------------------------------------------------------------
// Phase 2. grid (16, 64), 256 thr (warps: 2 n x 4 e; warp tile 64n x 32e).
// dyn smem: QH 0 (32K), QL 32K, BH 64K, BL 96K, RED 128K(2K), SCL +2K.
// Output staged back into [0,64K) with 512B swizzled rows.
// ---------------------------------------------------------------------------
#define SMEM2 (131072 + 2048 + 512)

__global__ __launch_bounds__(256, 1)
void phase2(const float* __restrict__ Q, float* __restrict__ O) {
    extern __shared__ char sm2[];
    const u32 sb = smem_u32(sm2);
    const int tid = threadIdx.x, lane = tid & 31, wid = tid >> 5;
    const int ntile = blockIdx.x, bh = blockIdx.y;
    const int m_base = (wid >> 2) * 64, e_base = (wid & 3) * 32;

    // B: raw copy of pre-swizzled KV tiles
    const float4* gh = (const float4*)(g_kvh + (size_t)bh * 8192);
    const float4* gl = (const float4*)(g_kvl + (size_t)bh * 8192);
#pragma unroll
    for (int it = 0; it < 8; it++) {
        ((float4*)(sm2 + 65536))[tid + it * 256] = gh[tid + it * 256];
        ((float4*)(sm2 + 98304))[tid + it * 256] = gl[tid + it * 256];
    }
    // A: load + act + hi/lo, natural [n][d] layout
    const float4* Q4 = (const float4*)Q + ((size_t)bh * SEQ + (size_t)ntile * 128) * 32;
#pragma unroll
    for (int it = 0; it < 16; it++) {
        int flat = tid + it * 256;
        int row = flat >> 5, fd = flat & 31;
        float4 q = Q4[flat];
        u32 h0, l0, h1, l1;
        hilo(actf(q.x), actf(q.y), h0, l0);
        hilo(actf(q.z), actf(q.w), h1, l1);
        int off = sw_addr(row, fd * 4);
        *(u64*)(sm2 + off)         = (u64)h0 | ((u64)h1 << 32);
        *(u64*)(sm2 + 32768 + off) = (u64)l0 | ((u64)l1 << 32);
    }
    __syncthreads();

    float acc[4][4][4];
#pragma unroll
    for (int i = 0; i < 4; i++)
#pragma unroll
        for (int j = 0; j < 4; j++)
#pragma unroll
            for (int q = 0; q < 4; q++) acc[i][j][q] = 0.f;

    const int a_row_l = ((lane >> 3) & 1) * 8 + (lane & 7);   // non-trans A
    const int a_col_l = ((lane >> 4) & 1) * 8;
    const int b_row_l = ((lane >> 3) & 1) * 8 + (lane & 7);   // trans B
    const int b_col_l = ((lane >> 4) & 1) * 8;

#pragma unroll
    for (int ks = 0; ks < 8; ks++) {
        int d0 = ks * 16;
        u32 ah[4][4], al[4][4];
#pragma unroll
        for (int mt = 0; mt < 4; mt++) {
            u32 ad = sb + sw_addr(m_base + mt * 16 + a_row_l, d0 + a_col_l);
            LDSM4(ah[mt][0], ah[mt][1], ah[mt][2], ah[mt][3], ad);
            LDSM4(al[mt][0], al[mt][1], al[mt][2], al[mt][3], ad + 32768);
        }
        u32 bhf[4][2], blf[4][2];
#pragma unroll
        for (int h = 0; h < 2; h++) {
            u32 ad = sb + 65536 + sw_addr(d0 + b_row_l, e_base + h * 16 + b_col_l);
            u32 r0, r1, r2, r3;
            LDSM4T(r0, r1, r2, r3, ad);
            bhf[2 * h][0] = r0; bhf[2 * h][1] = r1;
            bhf[2 * h + 1][0] = r2; bhf[2 * h + 1][1] = r3;
            LDSM4T(r0, r1, r2, r3, ad + 32768);
            blf[2 * h][0] = r0; blf[2 * h][1] = r1;
            blf[2 * h + 1][0] = r2; blf[2 * h + 1][1] = r3;
        }
#pragma unroll
        for (int mt = 0; mt < 4; mt++)
#pragma unroll
            for (int nt = 0; nt < 4; nt++) {
                mma16816(acc[mt][nt], ah[mt], bhf[nt]);
                mma16816(acc[mt][nt], ah[mt], blf[nt]);
                mma16816(acc[mt][nt], al[mt], bhf[nt]);
            }
    }
    __syncthreads();   // all warps done reading Q/KV tiles

    // RMS partials: quad shfl-reduce, then cross-warp via RED[128][4]
    float* RED = (float*)(sm2 + 131072);
#pragma unroll
    for (int mt = 0; mt < 4; mt++) {
        float s0 = 0.f, s1 = 0.f;
#pragma unroll
        for (int nt = 0; nt < 4; nt++) {
            s0 += acc[mt][nt][0] * acc[mt][nt][0] + acc[mt][nt][1] * acc[mt][nt][1];
            s1 += acc[mt][nt][2] * acc[mt][nt][2] + acc[mt][nt][3] * acc[mt][nt][3];
        }
        s0 += __shfl_xor_sync(0xFFFFFFFFu, s0, 1);
        s0 += __shfl_xor_sync(0xFFFFFFFFu, s0, 2);
        s1 += __shfl_xor_sync(0xFFFFFFFFu, s1, 1);
        s1 += __shfl_xor_sync(0xFFFFFFFFu, s1, 2);
        if ((lane & 3) == 0) {
            int r = m_base + mt * 16 + (lane >> 2);
            RED[r * 4 + (wid & 3)]       = s0;
            RED[(r + 8) * 4 + (wid & 3)] = s1;
        }
    }
    // stage outputs (swizzled 512B rows) into [0, 64K)
#pragma unroll
    for (int mt = 0; mt < 4; mt++)
#pragma unroll
        for (int nt = 0; nt < 4; nt++) {
            int r = m_base + mt * 16 + (lane >> 2);
            int e = e_base + nt * 8 + (lane & 3) * 2;
            *(float2*)(sm2 + os_addr(r, e)) =
                make_float2(acc[mt][nt][0], acc[mt][nt][1]);
            *(float2*)(sm2 + os_addr(r + 8, e)) =
                make_float2(acc[mt][nt][2], acc[mt][nt][3]);
        }
    __syncthreads();

    float* SCL = (float*)(sm2 + 131072 + 2048);
    if (tid < 128) {
        float s = RED[tid * 4] + RED[tid * 4 + 1] + RED[tid * 4 + 2] + RED[tid * 4 + 3];
        SCL[tid] = rsqrtf(s * (1.0f / 128.0f) + 1e-6f);
    }
    __syncthreads();

    float4* Ob = (float4*)(O + ((size_t)bh * SEQ + (size_t)ntile * 128) * 128);
#pragma unroll
    for (int it = 0; it < 16; it++) {
        int flat = tid + it * 256;
        int row = flat >> 5, fd = flat & 31;
        float4 v = *(const float4*)(sm2 + os_addr(row, fd * 4));
        float sc = SCL[row];
        Ob[flat] = make_float4(v.x * sc, v.y * sc, v.z * sc, v.w * sc);
    }
}

// ---------------------------------------------------------------------------
extern "C" void kernel_launch(void* const* d_in, const int* in_sizes, int n_in,
                              void* d_out, int out_size) {
    const float* Q    = (const float*)d_in[0];
    const float* K    = (const float*)d_in[1];
    const float* V    = (const float*)d_in[2];
    const float* mask = (const float*)d_in[3];
    float*       O    = (float*)d_out;

    cudaFuncSetAttribute(phase2, cudaFuncAttributeMaxDynamicSharedMemorySize, SMEM2);

    phase1<<<dim3(SPLITS, NBH), 256>>>(K, V, mask);
    midk<<<NBH, 256>>>();
    phase2<<<dim3(16, NBH), 256, SMEM2>>>(Q, O);
}

// round 10
// speedup vs baseline: 2.3802x; 1.8242x over previous
#include <cuda_runtime.h>
#include <cuda_bf16.h>

// NormSelfAttention B=4,H=16,N=2048,D=128 via mma.sync bf16x3 + cp.async
// deep staging (memory-latency fix over R7).
//  Phase1: KVpart[d,e] = sum_n (elu(K)+1)*m [n,d] * (V*m)[n,e]   split-K=4
//  Mid:    KV = sum splits -> pre-swizzled bf16 hi/lo tiles
//  Phase2: out[n,e] = sum_d (elu(Q)+1)[n,d]*KV[d,e]; fused RMS norm

#define SEQ    2048
#define NBH    64
#define SPLITS 4

__device__ float    g_kvpart[(size_t)NBH * SPLITS * 128 * 128];  // 16 MB
__device__ unsigned g_kvh[(size_t)NBH * 8192];                   // 2 MB
__device__ unsigned g_kvl[(size_t)NBH * 8192];                   // 2 MB

typedef unsigned u32;
typedef unsigned long long u64;

static __device__ __forceinline__ u32 smem_u32(const void* p) {
    u32 a;
    asm("{ .reg .u64 t; cvta.to.shared.u64 t, %1; cvt.u32.u64 %0, t; }"
        : "=r"(a) : "l"(p));
    return a;
}
static __device__ __forceinline__ float actf(float x) {
    return x > 0.0f ? x + 1.0f : __expf(x);
}
// hi = {bf16(x1),bf16(x0)}, lo = packed bf16 residuals (residual exact in f32)
static __device__ __forceinline__ void hilo(float x0, float x1, u32& h, u32& l) {
    asm("cvt.rn.bf16x2.f32 %0, %1, %2;" : "=r"(h) : "f"(x1), "f"(x0));
    float f0 = __uint_as_float(h << 16);
    float f1 = __uint_as_float(h & 0xFFFF0000u);
    asm("cvt.rn.bf16x2.f32 %0, %1, %2;" : "=r"(l) : "f"(x1 - f1), "f"(x0 - f0));
}
// 256B-row tile, xor-swizzled 16B units. col in b16 elements.
static __device__ __forceinline__ int sw_addr(int row, int col) {
    return (row << 8) + ((((col >> 3) ^ (row & 7)) << 4)) + ((col & 7) << 1);
}
// 512B-row f32 staging tile. col in f32 elements.
static __device__ __forceinline__ int os_addr(int row, int col) {
    return (row << 9) + ((((col >> 2) ^ (row & 7)) << 4)) + ((col & 3) << 2);
}

#define CP_A16(dst, src) \
    asm volatile("cp.async.cg.shared.global [%0], [%1], 16;" \
        :: "r"((u32)(dst)), "l"(src) : "memory")
#define CP_COMMIT() asm volatile("cp.async.commit_group;" ::: "memory")
#define CP_WAIT(n)  asm volatile("cp.async.wait_group %0;" :: "n"(n) : "memory")

#define LDSM4(r0, r1, r2, r3, a)                                              \
    asm volatile("ldmatrix.sync.aligned.m8n8.x4.shared.b16 {%0,%1,%2,%3}, [%4];" \
        : "=r"(r0), "=r"(r1), "=r"(r2), "=r"(r3) : "r"(a))
#define LDSM4T(r0, r1, r2, r3, a)                                             \
    asm volatile("ldmatrix.sync.aligned.m8n8.x4.trans.shared.b16 {%0,%1,%2,%3}, [%4];" \
        : "=r"(r0), "=r"(r1), "=r"(r2), "=r"(r3) : "r"(a))

static __device__ __forceinline__ void mma16816(float* c, const u32* a, const u32* b) {
    asm volatile(
        "mma.sync.aligned.m16n8k16.row.col.f32.bf16.bf16.f32 "
        "{%0,%1,%2,%3}, {%4,%5,%6,%7}, {%8,%9}, {%0,%1,%2,%3};"
        : "+f"(c[0]), "+f"(c[1]), "+f"(c[2]), "+f"(c[3])
        : "r"(a[0]), "r"(a[1]), "r"(a[2]), "r"(a[3]), "r"(b[0]), "r"(b[1]));
}

// ---------------------------------------------------------------------------
// Phase 1. grid (4, 64), 256 thr (8 warps: 2 d x 4 e; warp tile 64d x 32e).
// dyn smem: bf16 tiles KH 0 / KL 8K / VH 16K / VL 24K;
// raw cp.async stages at 32K: 3 x 33024B (K 16K | V 16K | mask 128B).
// ---------------------------------------------------------------------------
#define P1_STAGE(s) (32768 + (s) * 33024)
#define SMEM1 (32768 + 3 * 33024)

__global__ __launch_bounds__(256, 1)
void phase1(const float* __restrict__ K, const float* __restrict__ V,
            const float* __restrict__ mask) {
    extern __shared__ char sm1[];
    const u32 sb = smem_u32(sm1);
    const int tid = threadIdx.x, lane = tid & 31, wid = tid >> 5;
    const int split = blockIdx.x, bh = blockIdx.y, b = bh >> 4;
    const int d_base = (wid >> 2) * 64, e_base = (wid & 3) * 32;

    float acc[4][4][4];
#pragma unroll
    for (int i = 0; i < 4; i++)
#pragma unroll
        for (int j = 0; j < 4; j++)
#pragma unroll
            for (int q = 0; q < 4; q++) acc[i][j][q] = 0.f;

    const float4* K4 = (const float4*)K + (size_t)bh * (SEQ * 32) + (size_t)split * (512 * 32);
    const float4* V4 = (const float4*)V + (size_t)bh * (SEQ * 32) + (size_t)split * (512 * 32);
    const float4* M4 = (const float4*)(mask + b * SEQ + split * 512);

    // ldmatrix lane address components
    const int a_row_l = ((lane >> 4) & 1) * 8 + (lane & 7);   // trans A
    const int a_col_l = ((lane >> 3) & 1) * 8;
    const int b_row_l = ((lane >> 3) & 1) * 8 + (lane & 7);   // trans B
    const int b_col_l = ((lane >> 4) & 1) * 8;

    auto issue = [&](int c) {
        int st = P1_STAGE(c % 3);
        const float4* ks = K4 + (size_t)c * 1024;
        const float4* vs = V4 + (size_t)c * 1024;
#pragma unroll
        for (int it = 0; it < 4; it++) {
            int flat = tid + it * 256;
            CP_A16(sb + st + flat * 16, ks + flat);
            CP_A16(sb + st + 16384 + flat * 16, vs + flat);
        }
        if (tid < 8) CP_A16(sb + st + 32768 + tid * 16, M4 + c * 8 + tid);
        CP_COMMIT();
    };

    issue(0); issue(1); issue(2);

    for (int c = 0; c < 16; c++) {
        CP_WAIT(2);
        __syncthreads();
        {   // convert raw stage -> bf16 hi/lo swizzled tiles
            int st = P1_STAGE(c % 3);
            const float* mk = (const float*)(sm1 + st + 32768);
#pragma unroll
            for (int it = 0; it < 4; it++) {
                int flat = tid + it * 256;
                int row  = flat >> 5;      // n local 0..31
                int fd   = flat & 31;      // d/4
                float m  = mk[row];
                float4 kq = *(const float4*)(sm1 + st + row * 512 + fd * 16);
                float4 vq = *(const float4*)(sm1 + st + 16384 + row * 512 + fd * 16);
                u32 h0, l0, h1, l1;
                int off = sw_addr(row, fd * 4);
                hilo(actf(kq.x) * m, actf(kq.y) * m, h0, l0);
                hilo(actf(kq.z) * m, actf(kq.w) * m, h1, l1);
                *(u64*)(sm1 + off)         = (u64)h0 | ((u64)h1 << 32);
                *(u64*)(sm1 + 8192 + off)  = (u64)l0 | ((u64)l1 << 32);
                hilo(vq.x * m, vq.y * m, h0, l0);
                hilo(vq.z * m, vq.w * m, h1, l1);
                *(u64*)(sm1 + 16384 + off) = (u64)h0 | ((u64)h1 << 32);
                *(u64*)(sm1 + 24576 + off) = (u64)l0 | ((u64)l1 << 32);
            }
        }
        __syncthreads();                   // tiles ready; raw stage free
        if (c + 3 < 16) issue(c + 3); else CP_COMMIT();

#pragma unroll
        for (int ks = 0; ks < 2; ks++) {
            int n0 = ks * 16;
            u32 ah[4][4], al[4][4];
#pragma unroll
            for (int mt = 0; mt < 4; mt++) {
                u32 ad = sb + sw_addr(n0 + a_row_l, d_base + mt * 16 + a_col_l);
                LDSM4T(ah[mt][0], ah[mt][1], ah[mt][2], ah[mt][3], ad);
                LDSM4T(al[mt][0], al[mt][1], al[mt][2], al[mt][3], ad + 8192);
            }
            u32 bhf[4][2], blf[4][2];
#pragma unroll
            for (int h = 0; h < 2; h++) {
                u32 ad = sb + 16384 + sw_addr(n0 + b_row_l, e_base + h * 16 + b_col_l);
                u32 r0, r1, r2, r3;
                LDSM4T(r0, r1, r2, r3, ad);
                bhf[2 * h][0] = r0; bhf[2 * h][1] = r1;
                bhf[2 * h + 1][0] = r2; bhf[2 * h + 1][1] = r3;
                LDSM4T(r0, r1, r2, r3, ad + 8192);
                blf[2 * h][0] = r0; blf[2 * h][1] = r1;
                blf[2 * h + 1][0] = r2; blf[2 * h + 1][1] = r3;
            }
#pragma unroll
            for (int mt = 0; mt < 4; mt++)
#pragma unroll
                for (int nt = 0; nt < 4; nt++) {
                    mma16816(acc[mt][nt], ah[mt], bhf[nt]);
                    mma16816(acc[mt][nt], ah[mt], blf[nt]);
                    mma16816(acc[mt][nt], al[mt], bhf[nt]);
                }
        }
    }

    float* outp = g_kvpart + ((size_t)(bh * SPLITS + split)) * 16384;
#pragma unroll
    for (int mt = 0; mt < 4; mt++)
#pragma unroll
        for (int nt = 0; nt < 4; nt++) {
            int d1 = d_base + mt * 16 + (lane >> 2);
            int e  = e_base + nt * 8 + (lane & 3) * 2;
            *(float2*)(outp + d1 * 128 + e) =
                make_float2(acc[mt][nt][0], acc[mt][nt][1]);
            *(float2*)(outp + (d1 + 8) * 128 + e) =
                make_float2(acc[mt][nt][2], acc[mt][nt][3]);
        }
}

// ---------------------------------------------------------------------------
// Mid. grid 256, 256 thr. Sum 4 splits, emit pre-swizzled bf16 hi/lo tiles.
// ---------------------------------------------------------------------------
__global__ __launch_bounds__(256)
void midk() {
    const int tid = threadIdx.x;
#pragma unroll
    for (int i = 0; i < 8; i++) {
        int idx = blockIdx.x * 2048 + i * 256 + tid;   // 0..524287
        int bh = idx >> 13;
        int p  = idx & 8191;
        int d = p >> 6, e = (p & 63) * 2;
        const float* src = g_kvpart + (size_t)bh * (SPLITS * 16384);
        float sx = 0.f, sy = 0.f;
#pragma unroll
        for (int s = 0; s < SPLITS; s++) {
            float2 v = *(const float2*)(src + s * 16384 + d * 128 + e);
            sx += v.x; sy += v.y;
        }
        u32 h, l; hilo(sx, sy, h, l);
        int o = sw_addr(d, e) >> 2;
        g_kvh[(size_t)bh * 8192 + o] = h;
        g_kvl[(size_t)bh * 8192 + o] = l;
    }
}

// ---------------------------------------------------------------------------
// Phase 2. grid (16, 64), 256 thr (warps: 2 n x 4 e; warp tile 64n x 32e).
// dyn smem: QH 0 / QL 32K / KVH 64K / KVL 96K / QRAW 128K (64K, also output
// staging) / RED 192K / SCL +2K.
// cp.async groups: g0 = KV tiles, g1..g4 = Q raw chunks (128n x 32d each).
// ---------------------------------------------------------------------------
#define P2_QRAW 131072
#define P2_RED  196608
#define P2_SCL  198656
#define SMEM2   199168

__global__ __launch_bounds__(256, 1)
void phase2(const float* __restrict__ Q, float* __restrict__ O) {
    extern __shared__ char sm2[];
    const u32 sb = smem_u32(sm2);
    const int tid = threadIdx.x, lane = tid & 31, wid = tid >> 5;
    const int ntile = blockIdx.x, bh = blockIdx.y;
    const int m_base = (wid >> 2) * 64, e_base = (wid & 3) * 32;

    const float4* gh = (const float4*)(g_kvh + (size_t)bh * 8192);
    const float4* gl = (const float4*)(g_kvl + (size_t)bh * 8192);
    const float4* Q4 = (const float4*)Q + ((size_t)bh * SEQ + (size_t)ntile * 128) * 32;

    // g0: KV tiles (raw pre-swizzled copies)
#pragma unroll
    for (int it = 0; it < 8; it++) {
        int flat = tid + it * 256;
        CP_A16(sb + 65536 + flat * 16, gh + flat);
        CP_A16(sb + 98304 + flat * 16, gl + flat);
    }
    CP_COMMIT();
    // g1..g4: Q raw chunks
#pragma unroll
    for (int j = 0; j < 4; j++) {
#pragma unroll
        for (int it = 0; it < 4; it++) {
            int flat = tid + it * 256;
            int n = flat >> 3, fdl = flat & 7;
            CP_A16(sb + P2_QRAW + j * 16384 + n * 128 + fdl * 16,
                   Q4 + n * 32 + j * 8 + fdl);
        }
        CP_COMMIT();
    }

    float acc[4][4][4];
#pragma unroll
    for (int i = 0; i < 4; i++)
#pragma unroll
        for (int j = 0; j < 4; j++)
#pragma unroll
            for (int q = 0; q < 4; q++) acc[i][j][q] = 0.f;

    const int a_row_l = ((lane >> 3) & 1) * 8 + (lane & 7);   // non-trans A
    const int a_col_l = ((lane >> 4) & 1) * 8;
    const int b_row_l = ((lane >> 3) & 1) * 8 + (lane & 7);   // trans B
    const int b_col_l = ((lane >> 4) & 1) * 8;

#define P2_STEP(J, WAITN)                                                       \
    do {                                                                        \
        CP_WAIT(WAITN);                                                         \
        __syncthreads();                                                        \
        _Pragma("unroll")                                                       \
        for (int it = 0; it < 4; it++) {                                        \
            int flat = tid + it * 256;                                          \
            int n = flat >> 3, fdl = flat & 7;                                  \
            float4 q = *(const float4*)(sm2 + P2_QRAW + (J) * 16384             \
                                        + n * 128 + fdl * 16);                  \
            u32 h0, l0, h1, l1;                                                 \
            hilo(actf(q.x), actf(q.y), h0, l0);                                 \
            hilo(actf(q.z), actf(q.w), h1, l1);                                 \
            int off = sw_addr(n, ((J) * 8 + fdl) * 4);                          \
            *(u64*)(sm2 + off)         = (u64)h0 | ((u64)h1 << 32);             \
            *(u64*)(sm2 + 32768 + off) = (u64)l0 | ((u64)l1 << 32);             \
        }                                                                       \
        __syncthreads();                                                        \
        _Pragma("unroll")                                                       \
        for (int ks2 = 0; ks2 < 2; ks2++) {                                     \
            int d0 = (J) * 32 + ks2 * 16;                                       \
            u32 ah[4][4], al[4][4];                                             \
            _Pragma("unroll")                                                   \
            for (int mt = 0; mt < 4; mt++) {                                    \
                u32 ad = sb + sw_addr(m_base + mt * 16 + a_row_l, d0 + a_col_l);\
                LDSM4(ah[mt][0], ah[mt][1], ah[mt][2], ah[mt][3], ad);          \
                LDSM4(al[mt][0], al[mt][1], al[mt][2], al[mt][3], ad + 32768);  \
            }                                                                   \
            u32 bhf[4][2], blf[4][2];                                           \
            _Pragma("unroll")                                                   \
            for (int h = 0; h < 2; h++) {                                       \
                u32 ad = sb + 65536 + sw_addr(d0 + b_row_l,                     \
                                              e_base + h * 16 + b_col_l);       \
                u32 r0, r1, r2, r3;                                             \
                LDSM4T(r0, r1, r2, r3, ad);                                     \
                bhf[2 * h][0] = r0; bhf[2 * h][1] = r1;                         \
                bhf[2 * h + 1][0] = r2; bhf[2 * h + 1][1] = r3;                 \
                LDSM4T(r0, r1, r2, r3, ad + 32768);                             \
                blf[2 * h][0] = r0; blf[2 * h][1] = r1;                         \
                blf[2 * h + 1][0] = r2; blf[2 * h + 1][1] = r3;                 \
            }                                                                   \
            _Pragma("unroll")                                                   \
            for (int mt = 0; mt < 4; mt++)                                      \
                _Pragma("unroll")                                               \
                for (int nt = 0; nt < 4; nt++) {                                \
                    mma16816(acc[mt][nt], ah[mt], bhf[nt]);                     \
                    mma16816(acc[mt][nt], ah[mt], blf[nt]);                     \
                    mma16816(acc[mt][nt], al[mt], bhf[nt]);                     \
                }                                                               \
        }                                                                       \
    } while (0)

    P2_STEP(0, 3);
    P2_STEP(1, 2);
    P2_STEP(2, 1);
    P2_STEP(3, 0);
#undef P2_STEP

    // RMS partials: quad shfl-reduce -> RED[128][4]; stage outputs into QRAW
    float* RED = (float*)(sm2 + P2_RED);
#pragma unroll
    for (int mt = 0; mt < 4; mt++) {
        float s0 = 0.f, s1 = 0.f;
#pragma unroll
        for (int nt = 0; nt < 4; nt++) {
            s0 += acc[mt][nt][0] * acc[mt][nt][0] + acc[mt][nt][1] * acc[mt][nt][1];
            s1 += acc[mt][nt][2] * acc[mt][nt][2] + acc[mt][nt][3] * acc[mt][nt][3];
        }
        s0 += __shfl_xor_sync(0xFFFFFFFFu, s0, 1);
        s0 += __shfl_xor_sync(0xFFFFFFFFu, s0, 2);
        s1 += __shfl_xor_sync(0xFFFFFFFFu, s1, 1);
        s1 += __shfl_xor_sync(0xFFFFFFFFu, s1, 2);
        if ((lane & 3) == 0) {
            int r = m_base + mt * 16 + (lane >> 2);
            RED[r * 4 + (wid & 3)]       = s0;
            RED[(r + 8) * 4 + (wid & 3)] = s1;
        }
    }
#pragma unroll
    for (int mt = 0; mt < 4; mt++)
#pragma unroll
        for (int nt = 0; nt < 4; nt++) {
            int r = m_base + mt * 16 + (lane >> 2);
            int e = e_base + nt * 8 + (lane & 3) * 2;
            *(float2*)(sm2 + P2_QRAW + os_addr(r, e)) =
                make_float2(acc[mt][nt][0], acc[mt][nt][1]);
            *(float2*)(sm2 + P2_QRAW + os_addr(r + 8, e)) =
                make_float2(acc[mt][nt][2], acc[mt][nt][3]);
        }
    __syncthreads();

    float* SCL = (float*)(sm2 + P2_SCL);
    if (tid < 128) {
        float s = RED[tid * 4] + RED[tid * 4 + 1] + RED[tid * 4 + 2] + RED[tid * 4 + 3];
        SCL[tid] = rsqrtf(s * (1.0f / 128.0f) + 1e-6f);
    }
    __syncthreads();

    float4* Ob = (float4*)(O + ((size_t)bh * SEQ + (size_t)ntile * 128) * 128);
#pragma unroll
    for (int it = 0; it < 16; it++) {
        int flat = tid + it * 256;
        int row = flat >> 5, fd = flat & 31;
        float4 v = *(const float4*)(sm2 + P2_QRAW + os_addr(row, fd * 4));
        float sc = SCL[row];
        Ob[flat] = make_float4(v.x * sc, v.y * sc, v.z * sc, v.w * sc);
    }
}

// ---------------------------------------------------------------------------
extern "C" void kernel_launch(void* const* d_in, const int* in_sizes, int n_in,
                              void* d_out, int out_size) {
    const float* Q    = (const float*)d_in[0];
    const float* K    = (const float*)d_in[1];
    const float* V    = (const float*)d_in[2];
    const float* mask = (const float*)d_in[3];
    float*       O    = (float*)d_out;

    cudaFuncSetAttribute(phase1, cudaFuncAttributeMaxDynamicSharedMemorySize, SMEM1);
    cudaFuncSetAttribute(phase2, cudaFuncAttributeMaxDynamicSharedMemorySize, SMEM2);

    phase1<<<dim3(SPLITS, NBH), 256, SMEM1>>>(K, V, mask);
    midk<<<256, 256>>>();
    phase2<<<dim3(16, NBH), 256, SMEM2>>>(Q, O);
}

// round 11
// speedup vs baseline: 3.0176x; 1.2678x over previous
#include <cuda_runtime.h>
#include <cuda_bf16.h>

// NormSelfAttention B=4,H=16,N=2048,D=128 — mma.sync bf16x3 + cp.async,
// occupancy-2 revision (R10 was 1 CTA/SM, convert/MMA serialized).
//  Phase1: KVpart[d,e] = sum_n (elu(K)+1)*m [n,d] * (V*m)[n,e]   split-K=8
//  Mid:    KV = sum splits -> pre-swizzled bf16 hi/lo tiles
//  Phase2: out[n,e] = sum_d (elu(Q)+1)[n,d]*KV[d,e]; fused RMS norm

#define SEQ    2048
#define NBH    64
#define SPLITS 8

__device__ float    g_kvpart[(size_t)NBH * SPLITS * 128 * 128];  // 32 MB
__device__ unsigned g_kvh[(size_t)NBH * 8192];                   // 2 MB
__device__ unsigned g_kvl[(size_t)NBH * 8192];                   // 2 MB

typedef unsigned u32;
typedef unsigned long long u64;

static __device__ __forceinline__ u32 smem_u32(const void* p) {
    u32 a;
    asm("{ .reg .u64 t; cvta.to.shared.u64 t, %1; cvt.u32.u64 %0, t; }"
        : "=r"(a) : "l"(p));
    return a;
}
static __device__ __forceinline__ float actf(float x) {
    return x > 0.0f ? x + 1.0f : __expf(x);
}
// hi = {bf16(x1),bf16(x0)}, lo = packed bf16 residuals (residual exact in f32)
static __device__ __forceinline__ void hilo(float x0, float x1, u32& h, u32& l) {
    asm("cvt.rn.bf16x2.f32 %0, %1, %2;" : "=r"(h) : "f"(x1), "f"(x0));
    float f0 = __uint_as_float(h << 16);
    float f1 = __uint_as_float(h & 0xFFFF0000u);
    asm("cvt.rn.bf16x2.f32 %0, %1, %2;" : "=r"(l) : "f"(x1 - f1), "f"(x0 - f0));
}
// 256B-row tile (128 cols bf16), xor-swizzled 16B units. col in b16 elems.
static __device__ __forceinline__ int sw_addr(int row, int col) {
    return (row << 8) + ((((col >> 3) ^ (row & 7)) << 4)) + ((col & 7) << 1);
}
// 64B-row tile (32 cols bf16): unit = (col>>3) ^ ((row>>1)&3); rows 2k,2k+1
// share a 128B line at different halves -> 8-row ldmatrix groups bank-free.
static __device__ __forceinline__ int sw64(int row, int col) {
    return (row << 6) + (((((col >> 3) & 3) ^ ((row >> 1) & 3)) << 4)) + ((col & 7) << 1);
}

#define CP_A16(dst, src) \
    asm volatile("cp.async.cg.shared.global [%0], [%1], 16;" \
        :: "r"((u32)(dst)), "l"(src) : "memory")
#define CP_COMMIT() asm volatile("cp.async.commit_group;" ::: "memory")
#define CP_WAIT(n)  asm volatile("cp.async.wait_group %0;" :: "n"(n) : "memory")

#define LDSM4(r0, r1, r2, r3, a)                                              \
    asm volatile("ldmatrix.sync.aligned.m8n8.x4.shared.b16 {%0,%1,%2,%3}, [%4];" \
        : "=r"(r0), "=r"(r1), "=r"(r2), "=r"(r3) : "r"(a))
#define LDSM4T(r0, r1, r2, r3, a)                                             \
    asm volatile("ldmatrix.sync.aligned.m8n8.x4.trans.shared.b16 {%0,%1,%2,%3}, [%4];" \
        : "=r"(r0), "=r"(r1), "=r"(r2), "=r"(r3) : "r"(a))

static __device__ __forceinline__ void mma16816(float* c, const u32* a, const u32* b) {
    asm volatile(
        "mma.sync.aligned.m16n8k16.row.col.f32.bf16.bf16.f32 "
        "{%0,%1,%2,%3}, {%4,%5,%6,%7}, {%8,%9}, {%0,%1,%2,%3};"
        : "+f"(c[0]), "+f"(c[1]), "+f"(c[2]), "+f"(c[3])
        : "r"(a[0]), "r"(a[1]), "r"(a[2]), "r"(a[3]), "r"(b[0]), "r"(b[1]));
}

// ---------------------------------------------------------------------------
// Phase 1. grid (8, 64), 256 thr (8 warps: 2 d x 4 e; warp tile 64d x 32e).
// Per CTA: 256 n in 8 chunks of 32.  occ 2.
// dyn smem: bf16 tiles KH 0 / KL 8K / VH 16K / VL 24K;
// raw cp.async stages at 32K: 2 x 33024B (K 16K | V 16K | mask 128B). 96.5KB
// ---------------------------------------------------------------------------
#define P1_STAGE(s) (32768 + (s) * 33024)
#define SMEM1 (32768 + 2 * 33024)

__global__ __launch_bounds__(256, 2)
void phase1(const float* __restrict__ K, const float* __restrict__ V,
            const float* __restrict__ mask) {
    extern __shared__ char sm1[];
    const u32 sb = smem_u32(sm1);
    const int tid = threadIdx.x, lane = tid & 31, wid = tid >> 5;
    const int split = blockIdx.x, bh = blockIdx.y, b = bh >> 4;
    const int d_base = (wid >> 2) * 64, e_base = (wid & 3) * 32;

    float acc[4][4][4];
#pragma unroll
    for (int i = 0; i < 4; i++)
#pragma unroll
        for (int j = 0; j < 4; j++)
#pragma unroll
            for (int q = 0; q < 4; q++) acc[i][j][q] = 0.f;

    const float4* K4 = (const float4*)K + (size_t)bh * (SEQ * 32) + (size_t)split * (256 * 32);
    const float4* V4 = (const float4*)V + (size_t)bh * (SEQ * 32) + (size_t)split * (256 * 32);
    const float4* M4 = (const float4*)(mask + b * SEQ + split * 256);

    const int a_row_l = ((lane >> 4) & 1) * 8 + (lane & 7);   // trans A
    const int a_col_l = ((lane >> 3) & 1) * 8;
    const int b_row_l = ((lane >> 3) & 1) * 8 + (lane & 7);   // trans B
    const int b_col_l = ((lane >> 4) & 1) * 8;

    auto issue = [&](int c) {
        int st = P1_STAGE(c & 1);
        const float4* ks = K4 + (size_t)c * 1024;
        const float4* vs = V4 + (size_t)c * 1024;
#pragma unroll
        for (int it = 0; it < 4; it++) {
            int flat = tid + it * 256;
            CP_A16(sb + st + flat * 16, ks + flat);
            CP_A16(sb + st + 16384 + flat * 16, vs + flat);
        }
        if (tid < 8) CP_A16(sb + st + 32768 + tid * 16, M4 + c * 8 + tid);
        CP_COMMIT();
    };

    issue(0); issue(1);

    for (int c = 0; c < 8; c++) {
        CP_WAIT(1);
        __syncthreads();
        {   // convert raw stage -> bf16 hi/lo swizzled tiles
            int st = P1_STAGE(c & 1);
            const float* mk = (const float*)(sm1 + st + 32768);
#pragma unroll
            for (int it = 0; it < 4; it++) {
                int flat = tid + it * 256;
                int row  = flat >> 5;      // n local 0..31
                int fd   = flat & 31;      // d/4
                float m  = mk[row];
                float4 kq = *(const float4*)(sm1 + st + row * 512 + fd * 16);
                float4 vq = *(const float4*)(sm1 + st + 16384 + row * 512 + fd * 16);
                u32 h0, l0, h1, l1;
                int off = sw_addr(row, fd * 4);
                hilo(actf(kq.x) * m, actf(kq.y) * m, h0, l0);
                hilo(actf(kq.z) * m, actf(kq.w) * m, h1, l1);
                *(u64*)(sm1 + off)         = (u64)h0 | ((u64)h1 << 32);
                *(u64*)(sm1 + 8192 + off)  = (u64)l0 | ((u64)l1 << 32);
                hilo(vq.x * m, vq.y * m, h0, l0);
                hilo(vq.z * m, vq.w * m, h1, l1);
                *(u64*)(sm1 + 16384 + off) = (u64)h0 | ((u64)h1 << 32);
                *(u64*)(sm1 + 24576 + off) = (u64)l0 | ((u64)l1 << 32);
            }
        }
        __syncthreads();                   // tiles ready; raw stage free
        if (c + 2 < 8) issue(c + 2); else CP_COMMIT();

#pragma unroll
        for (int ks = 0; ks < 2; ks++) {
            int n0 = ks * 16;
            u32 ah[4][4], al[4][4];
#pragma unroll
            for (int mt = 0; mt < 4; mt++) {
                u32 ad = sb + sw_addr(n0 + a_row_l, d_base + mt * 16 + a_col_l);
                LDSM4T(ah[mt][0], ah[mt][1], ah[mt][2], ah[mt][3], ad);
                LDSM4T(al[mt][0], al[mt][1], al[mt][2], al[mt][3], ad + 8192);
            }
            u32 bhf[4][2], blf[4][2];
#pragma unroll
            for (int h = 0; h < 2; h++) {
                u32 ad = sb + 16384 + sw_addr(n0 + b_row_l, e_base + h * 16 + b_col_l);
                u32 r0, r1, r2, r3;
                LDSM4T(r0, r1, r2, r3, ad);
                bhf[2 * h][0] = r0; bhf[2 * h][1] = r1;
                bhf[2 * h + 1][0] = r2; bhf[2 * h + 1][1] = r3;
                LDSM4T(r0, r1, r2, r3, ad + 8192);
                blf[2 * h][0] = r0; blf[2 * h][1] = r1;
                blf[2 * h + 1][0] = r2; blf[2 * h + 1][1] = r3;
            }
#pragma unroll
            for (int mt = 0; mt < 4; mt++)
#pragma unroll
                for (int nt = 0; nt < 4; nt++) {
                    mma16816(acc[mt][nt], ah[mt], bhf[nt]);
                    mma16816(acc[mt][nt], ah[mt], blf[nt]);
                    mma16816(acc[mt][nt], al[mt], bhf[nt]);
                }
        }
    }

    float* outp = g_kvpart + ((size_t)(bh * SPLITS + split)) * 16384;
#pragma unroll
    for (int mt = 0; mt < 4; mt++)
#pragma unroll
        for (int nt = 0; nt < 4; nt++) {
            int d1 = d_base + mt * 16 + (lane >> 2);
            int e  = e_base + nt * 8 + (lane & 3) * 2;
            *(float2*)(outp + d1 * 128 + e) =
                make_float2(acc[mt][nt][0], acc[mt][nt][1]);
            *(float2*)(outp + (d1 + 8) * 128 + e) =
                make_float2(acc[mt][nt][2], acc[mt][nt][3]);
        }
}

// ---------------------------------------------------------------------------
// Mid. grid 256, 256 thr. Sum 8 splits, emit pre-swizzled bf16 hi/lo tiles.
// ---------------------------------------------------------------------------
__global__ __launch_bounds__(256)
void midk() {
    const int tid = threadIdx.x;
#pragma unroll
    for (int i = 0; i < 8; i++) {
        int idx = blockIdx.x * 2048 + i * 256 + tid;   // 0..524287
        int bh = idx >> 13;
        int p  = idx & 8191;
        int d = p >> 6, e = (p & 63) * 2;
        const float* src = g_kvpart + (size_t)bh * (SPLITS * 16384);
        float sx = 0.f, sy = 0.f;
#pragma unroll
        for (int s = 0; s < SPLITS; s++) {
            float2 v = *(const float2*)(src + s * 16384 + d * 128 + e);
            sx += v.x; sy += v.y;
        }
        u32 h, l; hilo(sx, sy, h, l);
        int o = sw_addr(d, e) >> 2;
        g_kvh[(size_t)bh * 8192 + o] = h;
        g_kvl[(size_t)bh * 8192 + o] = l;
    }
}

// ---------------------------------------------------------------------------
// Phase 2. grid (32, 64), 256 thr (warps: 2 n x 4 e; warp tile 32n x 32e).
// 64-row n-tiles, occ 2.  dyn smem (105.25 KB):
//   KVH 0 / KVL 32K / QRAW 64K (ring 3 x 8K) / QH 88K (ring 2 x 4K) /
//   QL 96K (ring 2 x 4K) / RED 104K / SCL +1K.
// Q chunk = 64n x 32d. Each thread converts the region its own cp.async
// wrote -> no barrier between wait and convert. Direct scaled frag stores.
// ---------------------------------------------------------------------------
#define P2_QRAW 65536
#define P2_QH   90112
#define P2_QL   98304
#define P2_RED  106496
#define P2_SCL  107520
#define SMEM2   107776

__global__ __launch_bounds__(256, 2)
void phase2(const float* __restrict__ Q, float* __restrict__ O) {
    extern __shared__ char sm2[];
    const u32 sb = smem_u32(sm2);
    const int tid = threadIdx.x, lane = tid & 31, wid = tid >> 5;
    const int ntile = blockIdx.x, bh = blockIdx.y;
    const int m_base = (wid >> 2) * 32, e_base = (wid & 3) * 32;

    const float4* gh = (const float4*)(g_kvh + (size_t)bh * 8192);
    const float4* gl = (const float4*)(g_kvl + (size_t)bh * 8192);
    const float4* Q4 = (const float4*)Q + ((size_t)bh * SEQ + (size_t)ntile * 64) * 32;

    // group 0: KV tiles (raw pre-swizzled copies)
#pragma unroll
    for (int it = 0; it < 8; it++) {
        int flat = tid + it * 256;
        CP_A16(sb + flat * 16, gh + flat);
        CP_A16(sb + 32768 + flat * 16, gl + flat);
    }
    CP_COMMIT();
    // groups 1..3: Q raw chunks 0..2 (64n x 32d = 512 float4 each)
#pragma unroll
    for (int j = 0; j < 3; j++) {
#pragma unroll
        for (int it = 0; it < 2; it++) {
            int flat = tid + it * 256;
            int n = flat >> 3, fdl = flat & 7;
            CP_A16(sb + P2_QRAW + j * 8192 + n * 128 + fdl * 16,
                   Q4 + n * 32 + j * 8 + fdl);
        }
        CP_COMMIT();
    }

    float acc[2][4][4];
#pragma unroll
    for (int i = 0; i < 2; i++)
#pragma unroll
        for (int j = 0; j < 4; j++)
#pragma unroll
            for (int q = 0; q < 4; q++) acc[i][j][q] = 0.f;

    const int a_row_l = ((lane >> 3) & 1) * 8 + (lane & 7);   // non-trans A
    const int a_col_l = ((lane >> 4) & 1) * 8;
    const int b_row_l = ((lane >> 3) & 1) * 8 + (lane & 7);   // trans B
    const int b_col_l = ((lane >> 4) & 1) * 8;

#pragma unroll
    for (int J = 0; J < 4; J++) {
        CP_WAIT(2);   // completes: J=0 -> {KV,q0}; J -> qJ (empty-commit tail)
        // convert own raw region -> QH/QL ring slot (J&1)
#pragma unroll
        for (int it = 0; it < 2; it++) {
            int flat = tid + it * 256;
            int n = flat >> 3, fdl = flat & 7;
            float4 q = *(const float4*)(sm2 + P2_QRAW + (J % 3) * 8192
                                        + n * 128 + fdl * 16);
            u32 h0, l0, h1, l1;
            hilo(actf(q.x), actf(q.y), h0, l0);
            hilo(actf(q.z), actf(q.w), h1, l1);
            int off = sw64(n, fdl * 4);
            *(u64*)(sm2 + P2_QH + (J & 1) * 4096 + off) = (u64)h0 | ((u64)h1 << 32);
            *(u64*)(sm2 + P2_QL + (J & 1) * 4096 + off) = (u64)l0 | ((u64)l1 << 32);
        }
        __syncthreads();
        if (J == 0) {   // chunk 3 into raw slot 0
#pragma unroll
            for (int it = 0; it < 2; it++) {
                int flat = tid + it * 256;
                int n = flat >> 3, fdl = flat & 7;
                CP_A16(sb + P2_QRAW + n * 128 + fdl * 16,
                       Q4 + n * 32 + 24 + fdl);
            }
        }
        CP_COMMIT();

#pragma unroll
        for (int ks = 0; ks < 2; ks++) {
            int d0 = J * 32 + ks * 16;   // global d for B tile rows
            u32 ah[2][4], al[2][4];
#pragma unroll
            for (int mt = 0; mt < 2; mt++) {
                u32 ad = sb + P2_QH + (J & 1) * 4096
                       + sw64(m_base + mt * 16 + a_row_l, ks * 16 + a_col_l);
                LDSM4(ah[mt][0], ah[mt][1], ah[mt][2], ah[mt][3], ad);
                LDSM4(al[mt][0], al[mt][1], al[mt][2], al[mt][3], ad + 8192);
            }
            u32 bhf[4][2], blf[4][2];
#pragma unroll
            for (int h = 0; h < 2; h++) {
                u32 ad = sb + sw_addr(d0 + b_row_l, e_base + h * 16 + b_col_l);
                u32 r0, r1, r2, r3;
                LDSM4T(r0, r1, r2, r3, ad);
                bhf[2 * h][0] = r0; bhf[2 * h][1] = r1;
                bhf[2 * h + 1][0] = r2; bhf[2 * h + 1][1] = r3;
                LDSM4T(r0, r1, r2, r3, ad + 32768);
                blf[2 * h][0] = r0; blf[2 * h][1] = r1;
                blf[2 * h + 1][0] = r2; blf[2 * h + 1][1] = r3;
            }
#pragma unroll
            for (int mt = 0; mt < 2; mt++)
#pragma unroll
                for (int nt = 0; nt < 4; nt++) {
                    mma16816(acc[mt][nt], ah[mt], bhf[nt]);
                    mma16816(acc[mt][nt], ah[mt], blf[nt]);
                    mma16816(acc[mt][nt], al[mt], bhf[nt]);
                }
        }
    }

    // RMS: quad shfl-reduce -> RED[64][4] -> scale -> direct scaled stores
    float* RED = (float*)(sm2 + P2_RED);
#pragma unroll
    for (int mt = 0; mt < 2; mt++) {
        float s0 = 0.f, s1 = 0.f;
#pragma unroll
        for (int nt = 0; nt < 4; nt++) {
            s0 += acc[mt][nt][0] * acc[mt][nt][0] + acc[mt][nt][1] * acc[mt][nt][1];
            s1 += acc[mt][nt][2] * acc[mt][nt][2] + acc[mt][nt][3] * acc[mt][nt][3];
        }
        s0 += __shfl_xor_sync(0xFFFFFFFFu, s0, 1);
        s0 += __shfl_xor_sync(0xFFFFFFFFu, s0, 2);
        s1 += __shfl_xor_sync(0xFFFFFFFFu, s1, 1);
        s1 += __shfl_xor_sync(0xFFFFFFFFu, s1, 2);
        if ((lane & 3) == 0) {
            int r = m_base + mt * 16 + (lane >> 2);
            RED[r * 4 + (wid & 3)]       = s0;
            RED[(r + 8) * 4 + (wid & 3)] = s1;
        }
    }
    __syncthreads();
    float* SCL = (float*)(sm2 + P2_SCL);
    if (tid < 64) {
        float s = RED[tid * 4] + RED[tid * 4 + 1] + RED[tid * 4 + 2] + RED[tid * 4 + 3];
        SCL[tid] = rsqrtf(s * (1.0f / 128.0f) + 1e-6f);
    }
    __syncthreads();

    float* Ob = O + ((size_t)bh * SEQ + (size_t)ntile * 64) * 128;
#pragma unroll
    for (int mt = 0; mt < 2; mt++) {
        int r1 = m_base + mt * 16 + (lane >> 2);
        float sc1 = SCL[r1], sc2 = SCL[r1 + 8];
#pragma unroll
        for (int nt = 0; nt < 4; nt++) {
            int e = e_base + nt * 8 + (lane & 3) * 2;
            *(float2*)(Ob + (size_t)r1 * 128 + e) =
                make_float2(acc[mt][nt][0] * sc1, acc[mt][nt][1] * sc1);
            *(float2*)(Ob + (size_t)(r1 + 8) * 128 + e) =
                make_float2(acc[mt][nt][2] * sc2, acc[mt][nt][3] * sc2);
        }
    }
}

// ---------------------------------------------------------------------------
extern "C" void kernel_launch(void* const* d_in, const int* in_sizes, int n_in,
                              void* d_out, int out_size) {
    const float* Q    = (const float*)d_in[0];
    const float* K    = (const float*)d_in[1];
    const float* V    = (const float*)d_in[2];
    const float* mask = (const float*)d_in[3];
    float*       O    = (float*)d_out;

    cudaFuncSetAttribute(phase1, cudaFuncAttributeMaxDynamicSharedMemorySize, SMEM1);
    cudaFuncSetAttribute(phase2, cudaFuncAttributeMaxDynamicSharedMemorySize, SMEM2);

    phase1<<<dim3(SPLITS, NBH), 256, SMEM1>>>(K, V, mask);
    midk<<<256, 256>>>();
    phase2<<<dim3(32, NBH), 256, SMEM2>>>(Q, O);
}

// round 13
// speedup vs baseline: 3.2843x; 1.0884x over previous
#include <cuda_runtime.h>
#include <cuda_bf16.h>

// NormSelfAttention B=4,H=16,N=2048,D=128 — mma.sync bf16x3 + cp.async.
// R12: traffic/balance revision (split-4 single-wave phase1, 128-row phase2
// tiles halving KV refetch, fatter mid grid).
//  Phase1: KVpart[d,e] = sum_n (elu(K)+1)*m [n,d] * (V*m)[n,e]   split-K=4
//  Mid:    KV = sum splits -> pre-swizzled bf16 hi/lo tiles
//  Phase2: out[n,e] = sum_d (elu(Q)+1)[n,d]*KV[d,e]; fused RMS norm

#define SEQ    2048
#define NBH    64
#define SPLITS 4

__device__ float    g_kvpart[(size_t)NBH * SPLITS * 128 * 128];  // 16 MB
__device__ unsigned g_kvh[(size_t)NBH * 8192];                   // 2 MB
__device__ unsigned g_kvl[(size_t)NBH * 8192];                   // 2 MB

typedef unsigned u32;
typedef unsigned long long u64;

static __device__ __forceinline__ u32 smem_u32(const void* p) {
    u32 a;
    asm("{ .reg .u64 t; cvta.to.shared.u64 t, %1; cvt.u32.u64 %0, t; }"
        : "=r"(a) : "l"(p));
    return a;
}
static __device__ __forceinline__ float actf(float x) {
    return x > 0.0f ? x + 1.0f : __expf(x);
}
// hi = {bf16(x1),bf16(x0)}, lo = packed bf16 residuals (residual exact in f32)
static __device__ __forceinline__ void hilo(float x0, float x1, u32& h, u32& l) {
    asm("cvt.rn.bf16x2.f32 %0, %1, %2;" : "=r"(h) : "f"(x1), "f"(x0));
    float f0 = __uint_as_float(h << 16);
    float f1 = __uint_as_float(h & 0xFFFF0000u);
    asm("cvt.rn.bf16x2.f32 %0, %1, %2;" : "=r"(l) : "f"(x1 - f1), "f"(x0 - f0));
}
// 256B-row tile (128 cols bf16), xor-swizzled 16B units. col in b16 elems.
static __device__ __forceinline__ int sw_addr(int row, int col) {
    return (row << 8) + ((((col >> 3) ^ (row & 7)) << 4)) + ((col & 7) << 1);
}
// 32B-row tile (16 cols bf16): unit ^= (row>>2)&1 -> ldmatrix 8-row groups
// land on 8 distinct 16B banks (verified: {0,2,4,6,1,3,5,7} pattern).
static __device__ __forceinline__ int sw16(int row, int col) {
    return (row << 5) + (((((col >> 3) & 1) ^ ((row >> 2) & 1)) << 4)) + ((col & 7) << 1);
}

#define CP_A16(dst, src) \
    asm volatile("cp.async.cg.shared.global [%0], [%1], 16;" \
        :: "r"((u32)(dst)), "l"(src) : "memory")
#define CP_COMMIT() asm volatile("cp.async.commit_group;" ::: "memory")
#define CP_WAIT(n)  asm volatile("cp.async.wait_group %0;" :: "n"(n) : "memory")

#define LDSM4(r0, r1, r2, r3, a)                                              \
    asm volatile("ldmatrix.sync.aligned.m8n8.x4.shared.b16 {%0,%1,%2,%3}, [%4];" \
        : "=r"(r0), "=r"(r1), "=r"(r2), "=r"(r3) : "r"(a))
#define LDSM4T(r0, r1, r2, r3, a)                                             \
    asm volatile("ldmatrix.sync.aligned.m8n8.x4.trans.shared.b16 {%0,%1,%2,%3}, [%4];" \
        : "=r"(r0), "=r"(r1), "=r"(r2), "=r"(r3) : "r"(a))

static __device__ __forceinline__ void mma16816(float* c, const u32* a, const u32* b) {
    asm volatile(
        "mma.sync.aligned.m16n8k16.row.col.f32.bf16.bf16.f32 "
        "{%0,%1,%2,%3}, {%4,%5,%6,%7}, {%8,%9}, {%0,%1,%2,%3};"
        : "+f"(c[0]), "+f"(c[1]), "+f"(c[2]), "+f"(c[3])
        : "r"(a[0]), "r"(a[1]), "r"(a[2]), "r"(a[3]), "r"(b[0]), "r"(b[1]));
}

// ---------------------------------------------------------------------------
// Phase 1. grid (4, 64) = 256 CTAs -> single wave at occ 2.
// 8 warps: 2 d x 4 e; warp tile 64d x 32e.  Per CTA: 512 n in 16 chunks of 32.
// dyn smem: bf16 tiles KH 0 / KL 8K / VH 16K / VL 24K;
// raw cp.async stages at 32K: 2 x 33024B (K 16K | V 16K | mask 128B). 96.5KB
// ---------------------------------------------------------------------------
#define P1_STAGE(s) (32768 + (s) * 33024)
#define SMEM1 (32768 + 2 * 33024)

__global__ __launch_bounds__(256, 2)
void phase1(const float* __restrict__ K, const float* __restrict__ V,
            const float* __restrict__ mask) {
    extern __shared__ char sm1[];
    const u32 sb = smem_u32(sm1);
    const int tid = threadIdx.x, lane = tid & 31, wid = tid >> 5;
    const int split = blockIdx.x, bh = blockIdx.y, b = bh >> 4;
    const int d_base = (wid >> 2) * 64, e_base = (wid & 3) * 32;

    float acc[4][4][4];
#pragma unroll
    for (int i = 0; i < 4; i++)
#pragma unroll
        for (int j = 0; j < 4; j++)
#pragma unroll
            for (int q = 0; q < 4; q++) acc[i][j][q] = 0.f;

    const float4* K4 = (const float4*)K + (size_t)bh * (SEQ * 32) + (size_t)split * (512 * 32);
    const float4* V4 = (const float4*)V + (size_t)bh * (SEQ * 32) + (size_t)split * (512 * 32);
    const float4* M4 = (const float4*)(mask + b * SEQ + split * 512);

    const int a_row_l = ((lane >> 4) & 1) * 8 + (lane & 7);   // trans A
    const int a_col_l = ((lane >> 3) & 1) * 8;
    const int b_row_l = ((lane >> 3) & 1) * 8 + (lane & 7);   // trans B
    const int b_col_l = ((lane >> 4) & 1) * 8;

    auto issue = [&](int c) {
        int st = P1_STAGE(c & 1);
        const float4* ks = K4 + (size_t)c * 1024;
        const float4* vs = V4 + (size_t)c * 1024;
#pragma unroll
        for (int it = 0; it < 4; it++) {
            int flat = tid + it * 256;
            CP_A16(sb + st + flat * 16, ks + flat);
            CP_A16(sb + st + 16384 + flat * 16, vs + flat);
        }
        if (tid < 8) CP_A16(sb + st + 32768 + tid * 16, M4 + c * 8 + tid);
        CP_COMMIT();
    };

    issue(0); issue(1);

    for (int c = 0; c < 16; c++) {
        CP_WAIT(1);
        __syncthreads();
        {   // convert raw stage -> bf16 hi/lo swizzled tiles
            int st = P1_STAGE(c & 1);
            const float* mk = (const float*)(sm1 + st + 32768);
#pragma unroll
            for (int it = 0; it < 4; it++) {
                int flat = tid + it * 256;
                int row  = flat >> 5;      // n local 0..31
                int fd   = flat & 31;      // d/4
                float m  = mk[row];
                float4 kq = *(const float4*)(sm1 + st + row * 512 + fd * 16);
                float4 vq = *(const float4*)(sm1 + st + 16384 + row * 512 + fd * 16);
                u32 h0, l0, h1, l1;
                int off = sw_addr(row, fd * 4);
                hilo(actf(kq.x) * m, actf(kq.y) * m, h0, l0);
                hilo(actf(kq.z) * m, actf(kq.w) * m, h1, l1);
                *(u64*)(sm1 + off)         = (u64)h0 | ((u64)h1 << 32);
                *(u64*)(sm1 + 8192 + off)  = (u64)l0 | ((u64)l1 << 32);
                hilo(vq.x * m, vq.y * m, h0, l0);
                hilo(vq.z * m, vq.w * m, h1, l1);
                *(u64*)(sm1 + 16384 + off) = (u64)h0 | ((u64)h1 << 32);
                *(u64*)(sm1 + 24576 + off) = (u64)l0 | ((u64)l1 << 32);
            }
        }
        __syncthreads();                   // tiles ready; raw stage free
        if (c + 2 < 16) issue(c + 2); else CP_COMMIT();

#pragma unroll
        for (int ks = 0; ks < 2; ks++) {
            int n0 = ks * 16;
            u32 ah[4][4], al[4][4];
#pragma unroll
            for (int mt = 0; mt < 4; mt++) {
                u32 ad = sb + sw_addr(n0 + a_row_l, d_base + mt * 16 + a_col_l);
                LDSM4T(ah[mt][0], ah[mt][1], ah[mt][2], ah[mt][3], ad);
                LDSM4T(al[mt][0], al[mt][1], al[mt][2], al[mt][3], ad + 8192);
            }
            u32 bhf[4][2], blf[4][2];
#pragma unroll
            for (int h = 0; h < 2; h++) {
                u32 ad = sb + 16384 + sw_addr(n0 + b_row_l, e_base + h * 16 + b_col_l);
                u32 r0, r1, r2, r3;
                LDSM4T(r0, r1, r2, r3, ad);
                bhf[2 * h][0] = r0; bhf[2 * h][1] = r1;
                bhf[2 * h + 1][0] = r2; bhf[2 * h + 1][1] = r3;
                LDSM4T(r0, r1, r2, r3, ad + 8192);
                blf[2 * h][0] = r0; blf[2 * h][1] = r1;
                blf[2 * h + 1][0] = r2; blf[2 * h + 1][1] = r3;
            }
#pragma unroll
            for (int mt = 0; mt < 4; mt++)
#pragma unroll
                for (int nt = 0; nt < 4; nt++) {
                    mma16816(acc[mt][nt], ah[mt], bhf[nt]);
                    mma16816(acc[mt][nt], ah[mt], blf[nt]);
                    mma16816(acc[mt][nt], al[mt], bhf[nt]);
                }
        }
    }

    float* outp = g_kvpart + ((size_t)(bh * SPLITS + split)) * 16384;
#pragma unroll
    for (int mt = 0; mt < 4; mt++)
#pragma unroll
        for (int nt = 0; nt < 4; nt++) {
            int d1 = d_base + mt * 16 + (lane >> 2);
            int e  = e_base + nt * 8 + (lane & 3) * 2;
            *(float2*)(outp + d1 * 128 + e) =
                make_float2(acc[mt][nt][0], acc[mt][nt][1]);
            *(float2*)(outp + (d1 + 8) * 128 + e) =
                make_float2(acc[mt][nt][2], acc[mt][nt][3]);
        }
}

// ---------------------------------------------------------------------------
// Mid. grid 512, 256 thr. Sum 4 splits, emit pre-swizzled bf16 hi/lo tiles.
// ---------------------------------------------------------------------------
__global__ __launch_bounds__(256)
void midk() {
    const int tid = threadIdx.x;
#pragma unroll
    for (int i = 0; i < 4; i++) {
        int idx = blockIdx.x * 1024 + i * 256 + tid;   // 0..524287
        int bh = idx >> 13;
        int p  = idx & 8191;
        int d = p >> 6, e = (p & 63) * 2;
        const float* src = g_kvpart + (size_t)bh * (SPLITS * 16384);
        float sx = 0.f, sy = 0.f;
#pragma unroll
        for (int s = 0; s < SPLITS; s++) {
            float2 v = *(const float2*)(src + s * 16384 + d * 128 + e);
            sx += v.x; sy += v.y;
        }
        u32 h, l; hilo(sx, sy, h, l);
        int o = sw_addr(d, e) >> 2;
        g_kvh[(size_t)bh * 8192 + o] = h;
        g_kvl[(size_t)bh * 8192 + o] = l;
    }
}

// ---------------------------------------------------------------------------
// Phase 2. grid (16, 64) = 1024 CTAs, 128-row n-tiles, occ 2.
// 8 warps: 2 n x 4 e; warp tile 64n x 32e.  K split into 8 chunks of 16 d.
// dyn smem (~106.5KB): KVH 0 / KVL 32K / QRAW 64K (ring 3 x 8K) /
//   QH 88K (ring 2 x 4K) / QL 96K (ring 2 x 4K) / RED 104K / SCL 106K.
// One __syncthreads per J: convert reads the region this thread's own
// cp.async wrote; bf16 chunk tiles are double-buffered.
// ---------------------------------------------------------------------------
#define P2_QRAW 65536
#define P2_QH   90112
#define P2_QL   98304
#define P2_RED  106496
#define P2_SCL  108544
#define SMEM2   109056

__global__ __launch_bounds__(256, 2)
void phase2(const float* __restrict__ Q, float* __restrict__ O) {
    extern __shared__ char sm2[];
    const u32 sb = smem_u32(sm2);
    const int tid = threadIdx.x, lane = tid & 31, wid = tid >> 5;
    const int ntile = blockIdx.x, bh = blockIdx.y;
    const int m_base = (wid >> 2) * 64, e_base = (wid & 3) * 32;

    const float4* gh = (const float4*)(g_kvh + (size_t)bh * 8192);
    const float4* gl = (const float4*)(g_kvl + (size_t)bh * 8192);
    const float4* Q4 = (const float4*)Q + ((size_t)bh * SEQ + (size_t)ntile * 128) * 32;

    // group 0: KV tiles (raw pre-swizzled copies)
#pragma unroll
    for (int it = 0; it < 8; it++) {
        int flat = tid + it * 256;
        CP_A16(sb + flat * 16, gh + flat);
        CP_A16(sb + 32768 + flat * 16, gl + flat);
    }
    CP_COMMIT();
    // groups 1..3: Q raw chunks 0..2 (128n x 16d = 512 float4 each)
#pragma unroll
    for (int j = 0; j < 3; j++) {
#pragma unroll
        for (int it = 0; it < 2; it++) {
            int flat = tid + it * 256;
            int n = flat >> 2, fdl = flat & 3;
            CP_A16(sb + P2_QRAW + j * 8192 + n * 64 + fdl * 16,
                   Q4 + n * 32 + j * 4 + fdl);
        }
        CP_COMMIT();
    }

    float acc[4][4][4];
#pragma unroll
    for (int i = 0; i < 4; i++)
#pragma unroll
        for (int j = 0; j < 4; j++)
#pragma unroll
            for (int q = 0; q < 4; q++) acc[i][j][q] = 0.f;

    const int a_row_l = ((lane >> 3) & 1) * 8 + (lane & 7);   // non-trans A
    const int a_col_l = ((lane >> 4) & 1) * 8;
    const int b_row_l = ((lane >> 3) & 1) * 8 + (lane & 7);   // trans B
    const int b_col_l = ((lane >> 4) & 1) * 8;

#pragma unroll
    for (int J = 0; J < 8; J++) {
        CP_WAIT(2);          // raw chunk J (group J+1) complete
        // convert own raw region -> bf16 slot J&1 (thread-private mapping)
#pragma unroll
        for (int it = 0; it < 2; it++) {
            int flat = tid + it * 256;
            int n = flat >> 2, fdl = flat & 3;
            float4 q = *(const float4*)(sm2 + P2_QRAW + (J % 3) * 8192
                                        + n * 64 + fdl * 16);
            u32 h0, l0, h1, l1;
            hilo(actf(q.x), actf(q.y), h0, l0);
            hilo(actf(q.z), actf(q.w), h1, l1);
            int off = sw16(n, fdl * 4);
            *(u64*)(sm2 + P2_QH + (J & 1) * 4096 + off) = (u64)h0 | ((u64)h1 << 32);
            *(u64*)(sm2 + P2_QL + (J & 1) * 4096 + off) = (u64)l0 | ((u64)l1 << 32);
        }
        // refill raw slot J%3 with chunk J+3 (same thread-private region)
        if (J + 3 < 8) {
#pragma unroll
            for (int it = 0; it < 2; it++) {
                int flat = tid + it * 256;
                int n = flat >> 2, fdl = flat & 3;
                CP_A16(sb + P2_QRAW + (J % 3) * 8192 + n * 64 + fdl * 16,
                       Q4 + n * 32 + (J + 3) * 4 + fdl);
            }
        }
        CP_COMMIT();
        __syncthreads();

        // B fragments once per J (16 d rows), reused across 4 A subtiles
        u32 bhf[4][2], blf[4][2];
#pragma unroll
        for (int h = 0; h < 2; h++) {
            u32 ad = sb + sw_addr(J * 16 + b_row_l, e_base + h * 16 + b_col_l);
            u32 r0, r1, r2, r3;
            LDSM4T(r0, r1, r2, r3, ad);
            bhf[2 * h][0] = r0; bhf[2 * h][1] = r1;
            bhf[2 * h + 1][0] = r2; bhf[2 * h + 1][1] = r3;
            LDSM4T(r0, r1, r2, r3, ad + 32768);
            blf[2 * h][0] = r0; blf[2 * h][1] = r1;
            blf[2 * h + 1][0] = r2; blf[2 * h + 1][1] = r3;
        }
#pragma unroll
        for (int mt = 0; mt < 4; mt++) {
            u32 ah[4], al[4];
            u32 ad = sb + P2_QH + (J & 1) * 4096
                   + sw16(m_base + mt * 16 + a_row_l, a_col_l);
            LDSM4(ah[0], ah[1], ah[2], ah[3], ad);
            LDSM4(al[0], al[1], al[2], al[3], ad + 8192);
#pragma unroll
            for (int nt = 0; nt < 4; nt++) {
                mma16816(acc[mt][nt], ah, bhf[nt]);
                mma16816(acc[mt][nt], ah, blf[nt]);
                mma16816(acc[mt][nt], al, bhf[nt]);
            }
        }
    }

    // RMS: quad shfl-reduce -> RED[128][4] -> scale -> direct scaled stores
    float* RED = (float*)(sm2 + P2_RED);
#pragma unroll
    for (int mt = 0; mt < 4; mt++) {
        float s0 = 0.f, s1 = 0.f;
#pragma unroll
        for (int nt = 0; nt < 4; nt++) {
            s0 += acc[mt][nt][0] * acc[mt][nt][0] + acc[mt][nt][1] * acc[mt][nt][1];
            s1 += acc[mt][nt][2] * acc[mt][nt][2] + acc[mt][nt][3] * acc[mt][nt][3];
        }
        s0 += __shfl_xor_sync(0xFFFFFFFFu, s0, 1);
        s0 += __shfl_xor_sync(0xFFFFFFFFu, s0, 2);
        s1 += __shfl_xor_sync(0xFFFFFFFFu, s1, 1);
        s1 += __shfl_xor_sync(0xFFFFFFFFu, s1, 2);
        if ((lane & 3) == 0) {
            int r = m_base + mt * 16 + (lane >> 2);
            RED[r * 4 + (wid & 3)]       = s0;
            RED[(r + 8) * 4 + (wid & 3)] = s1;
        }
    }
    __syncthreads();
    float* SCL = (float*)(sm2 + P2_SCL);
    if (tid < 128) {
        float s = RED[tid * 4] + RED[tid * 4 + 1] + RED[tid * 4 + 2] + RED[tid * 4 + 3];
        SCL[tid] = rsqrtf(s * (1.0f / 128.0f) + 1e-6f);
    }
    __syncthreads();

    float* Ob = O + ((size_t)bh * SEQ + (size_t)ntile * 128) * 128;
#pragma unroll
    for (int mt = 0; mt < 4; mt++) {
        int r1 = m_base + mt * 16 + (lane >> 2);
        float sc1 = SCL[r1], sc2 = SCL[r1 + 8];
#pragma unroll
        for (int nt = 0; nt < 4; nt++) {
            int e = e_base + nt * 8 + (lane & 3) * 2;
            *(float2*)(Ob + (size_t)r1 * 128 + e) =
                make_float2(acc[mt][nt][0] * sc1, acc[mt][nt][1] * sc1);
            *(float2*)(Ob + (size_t)(r1 + 8) * 128 + e) =
                make_float2(acc[mt][nt][2] * sc2, acc[mt][nt][3] * sc2);
        }
    }
}

// ---------------------------------------------------------------------------
extern "C" void kernel_launch(void* const* d_in, const int* in_sizes, int n_in,
                              void* d_out, int out_size) {
    const float* Q    = (const float*)d_in[0];
    const float* K    = (const float*)d_in[1];
    const float* V    = (const float*)d_in[2];
    const float* mask = (const float*)d_in[3];
    float*       O    = (float*)d_out;

    cudaFuncSetAttribute(phase1, cudaFuncAttributeMaxDynamicSharedMemorySize, SMEM1);
    cudaFuncSetAttribute(phase2, cudaFuncAttributeMaxDynamicSharedMemorySize, SMEM2);

    phase1<<<dim3(SPLITS, NBH), 256, SMEM1>>>(K, V, mask);
    midk<<<512, 256>>>();
    phase2<<<dim3(16, NBH), 256, SMEM2>>>(Q, O);
}